// round 7
// baseline (speedup 1.0000x reference)
#include <cuda_runtime.h>
#include <math.h>

#define N_NODES 50000
#define N_EDGES 800000
#define AW 68                               // padded word stride (conflict-free)
#define NT64 ((N_NODES + 127) / 128)        // 391 tiles of 128 nodes
#define NT13 ((N_NODES + 63) / 64)          // 782 tiles of 64 nodes
#define SMEM_BYTES ((128 * AW * 2 + 64 * AW * 2 + 64) * 4)   // 104704

// ---------------- scratch (static device memory; no allocs) ----------------
__device__ int   g_bar_count;
__device__ volatile unsigned g_bar_gen;
__device__ int   g_counts[N_NODES];        // invariant: zero at kernel entry
__device__ int   g_rowptr[N_NODES + 1];
__device__ int   g_cursor[N_NODES];
__device__ int   g_bsum[1024];
__device__ int2  g_edge[N_EDGES];          // {src, weight-as-int}
__device__ float g_x16[N_NODES * 16];
__device__ float g_h[2][N_NODES * 64];
__device__ float g_aggr[N_NODES * 64];
__device__ float g_t[N_NODES];
__device__ float g_r[N_NODES];

// ---------------- helpers ----------------
__device__ __forceinline__ unsigned bf16_rn(float f) {
    unsigned u = __float_as_uint(f);
    return (u + 0x7fffu + ((u >> 16) & 1u)) >> 16;
}

__device__ __forceinline__ void mma_bf16(float* c,
                                         unsigned a0, unsigned a1, unsigned a2, unsigned a3,
                                         unsigned b0, unsigned b1) {
    asm volatile(
        "mma.sync.aligned.m16n8k16.row.col.f32.bf16.bf16.f32 "
        "{%0,%1,%2,%3}, {%4,%5,%6,%7}, {%8,%9}, {%0,%1,%2,%3};\n"
        : "+f"(c[0]), "+f"(c[1]), "+f"(c[2]), "+f"(c[3])
        : "r"(a0), "r"(a1), "r"(a2), "r"(a3), "r"(b0), "r"(b1));
}

// Software grid barrier. Safe because the grid is sized to guaranteed
// residency (occupancy query). __threadfence() is gpu-scope -> pushes writes
// to L2 and invalidates L1D, so post-barrier loads see predecessor output.
__device__ __forceinline__ void grid_bar() {
    __threadfence();
    __syncthreads();
    if (threadIdx.x == 0) {
        unsigned gen = g_bar_gen;
        if (atomicAdd(&g_bar_count, 1) == (int)gridDim.x - 1) {
            g_bar_count = 0;
            __threadfence();
            g_bar_gen = gen + 1;
        } else {
            while (g_bar_gen == gen) __nanosleep(64);
        }
    }
    __syncthreads();
}

// ---------------- phase bodies ----------------
__device__ void phase_aggr64(const float* __restrict__ h, int gw0, int stride) {
    const float4* __restrict__ h4 = (const float4*)h;
    int lane = threadIdx.x & 31, half = lane >> 4, sl = lane & 15;
    for (int w = gw0; w < N_NODES; w += stride) {
        int rs = __ldcg(&g_rowptr[w]), re = __ldcg(&g_rowptr[w + 1]);
        int i = rs + half;
        float4 a0 = make_float4(0.f, 0.f, 0.f, 0.f);
        float4 a1 = make_float4(0.f, 0.f, 0.f, 0.f);
        float4 a2 = make_float4(0.f, 0.f, 0.f, 0.f);
        float4 a3 = make_float4(0.f, 0.f, 0.f, 0.f);
        for (; i + 6 < re; i += 8) {
            int2 m0 = __ldcg(&g_edge[i]);
            int2 m1 = __ldcg(&g_edge[i + 2]);
            int2 m2 = __ldcg(&g_edge[i + 4]);
            int2 m3 = __ldcg(&g_edge[i + 6]);
            float4 v0 = __ldcg(h4 + m0.x * 16 + sl);
            float4 v1 = __ldcg(h4 + m1.x * 16 + sl);
            float4 v2 = __ldcg(h4 + m2.x * 16 + sl);
            float4 v3 = __ldcg(h4 + m3.x * 16 + sl);
            float w0 = __int_as_float(m0.y), w1 = __int_as_float(m1.y);
            float w2 = __int_as_float(m2.y), w3 = __int_as_float(m3.y);
            a0.x += w0 * v0.x; a0.y += w0 * v0.y; a0.z += w0 * v0.z; a0.w += w0 * v0.w;
            a1.x += w1 * v1.x; a1.y += w1 * v1.y; a1.z += w1 * v1.z; a1.w += w1 * v1.w;
            a2.x += w2 * v2.x; a2.y += w2 * v2.y; a2.z += w2 * v2.z; a2.w += w2 * v2.w;
            a3.x += w3 * v3.x; a3.y += w3 * v3.y; a3.z += w3 * v3.z; a3.w += w3 * v3.w;
        }
        for (; i < re; i += 2) {
            int2 m = __ldcg(&g_edge[i]);
            float4 v = __ldcg(h4 + m.x * 16 + sl);
            float ww = __int_as_float(m.y);
            a0.x += ww * v.x; a0.y += ww * v.y; a0.z += ww * v.z; a0.w += ww * v.w;
        }
        a0.x += a1.x + a2.x + a3.x;
        a0.y += a1.y + a2.y + a3.y;
        a0.z += a1.z + a2.z + a3.z;
        a0.w += a1.w + a2.w + a3.w;
        a0.x += __shfl_xor_sync(0xffffffffu, a0.x, 16);
        a0.y += __shfl_xor_sync(0xffffffffu, a0.y, 16);
        a0.z += __shfl_xor_sync(0xffffffffu, a0.z, 16);
        a0.w += __shfl_xor_sync(0xffffffffu, a0.w, 16);
        if (half == 0) ((float4*)(g_aggr + (size_t)w * 64))[sl] = a0;
    }
}

__device__ void phase_gemm64(const float* __restrict__ hin, float* __restrict__ hout,
                             const float* __restrict__ Wrel, const float* __restrict__ brel,
                             const float* __restrict__ Wroot,
                             const float* __restrict__ Wrel4, const float* __restrict__ b4,
                             const float* __restrict__ Wroot4,
                             bool final_, unsigned* smem_u) {
    unsigned* sAhi = smem_u;
    unsigned* sAlo = sAhi + 128 * AW;
    unsigned* sWhi = sAlo + 128 * AW;
    unsigned* sWlo = sWhi + 64 * AW;
    float*    sb   = (float*)(sWlo + 64 * AW);
    int tid = threadIdx.x;

    if (tid < 64) sb[tid] = __ldg(&brel[tid]);
    for (int p = tid; p < 64 * 64; p += 256) {    // W: input, never written
        int col = p >> 6, w = p & 63;
        int k = 2 * w;
        float f0, f1;
        if (k < 64) { f0 = __ldg(&Wrel[k * 64 + col]);         f1 = __ldg(&Wrel[(k + 1) * 64 + col]); }
        else        { f0 = __ldg(&Wroot[(k - 64) * 64 + col]); f1 = __ldg(&Wroot[(k - 63) * 64 + col]); }
        unsigned h0 = bf16_rn(f0), h1 = bf16_rn(f1);
        sWhi[col * AW + w] = h0 | (h1 << 16);
        sWlo[col * AW + w] = bf16_rn(f0 - __uint_as_float(h0 << 16)) |
                             (bf16_rn(f1 - __uint_as_float(h1 << 16)) << 16);
    }
    __syncthreads();

    int warp = tid >> 5, lane = tid & 31;
    int r = lane >> 2, q = lane & 3;
    int mb = warp * 16;

    for (int t = blockIdx.x; t < NT64; t += gridDim.x) {
        int nbase = t * 128;
        for (int p = tid; p < 128 * 32; p += 256) {
            int ln = p >> 5, w = p & 31;
            int node = nbase + ln;
            if (node >= N_NODES) node = N_NODES - 1;
            float2 va = __ldcg((const float2*)(g_aggr + (size_t)node * 64) + w);
            float2 vh = __ldcg((const float2*)(hin    + (size_t)node * 64) + w);
            {
                unsigned h0 = bf16_rn(va.x), h1 = bf16_rn(va.y);
                sAhi[ln * AW + w] = h0 | (h1 << 16);
                sAlo[ln * AW + w] = bf16_rn(va.x - __uint_as_float(h0 << 16)) |
                                    (bf16_rn(va.y - __uint_as_float(h1 << 16)) << 16);
            }
            {
                unsigned h0 = bf16_rn(vh.x), h1 = bf16_rn(vh.y);
                sAhi[ln * AW + 32 + w] = h0 | (h1 << 16);
                sAlo[ln * AW + 32 + w] = bf16_rn(vh.x - __uint_as_float(h0 << 16)) |
                                         (bf16_rn(vh.y - __uint_as_float(h1 << 16)) << 16);
            }
        }
        __syncthreads();

        float acc[8][4];
#pragma unroll
        for (int j = 0; j < 8; j++) {
            float b0 = sb[j * 8 + 2 * q], b1 = sb[j * 8 + 2 * q + 1];
            acc[j][0] = b0; acc[j][1] = b1; acc[j][2] = b0; acc[j][3] = b1;
        }
        int arow0 = (mb + r) * AW, arow1 = (mb + r + 8) * AW;
#pragma unroll
        for (int ks = 0; ks < 8; ks++) {
            int kw = ks * 8 + q;
            unsigned ah0 = sAhi[arow0 + kw],     ah1 = sAhi[arow1 + kw];
            unsigned ah2 = sAhi[arow0 + kw + 4], ah3 = sAhi[arow1 + kw + 4];
            unsigned al0 = sAlo[arow0 + kw],     al1 = sAlo[arow1 + kw];
            unsigned al2 = sAlo[arow0 + kw + 4], al3 = sAlo[arow1 + kw + 4];
#pragma unroll
            for (int j = 0; j < 8; j++) {
                int brow = (j * 8 + r) * AW + ks * 8 + q;
                unsigned bh0 = sWhi[brow], bh1 = sWhi[brow + 4];
                unsigned bl0 = sWlo[brow], bl1 = sWlo[brow + 4];
                mma_bf16(acc[j], ah0, ah1, ah2, ah3, bh0, bh1);
                mma_bf16(acc[j], ah0, ah1, ah2, ah3, bl0, bl1);
                mma_bf16(acc[j], al0, al1, al2, al3, bh0, bh1);
            }
        }

        int n0 = nbase + mb + r;
        int n1 = n0 + 8;
        if (final_) {
            float pt0 = 0.f, pr0 = 0.f, pt1 = 0.f, pr1 = 0.f;
#pragma unroll
            for (int j = 0; j < 8; j++) {
                int c = j * 8 + 2 * q;
                float w0 = __ldg(&Wrel4[c]),  w1 = __ldg(&Wrel4[c + 1]);
                float s0 = __ldg(&Wroot4[c]), s1 = __ldg(&Wroot4[c + 1]);
                float u;
                u = fmaxf(acc[j][0], 0.f); pt0 += u * w0; pr0 += u * s0;
                u = fmaxf(acc[j][1], 0.f); pt0 += u * w1; pr0 += u * s1;
                u = fmaxf(acc[j][2], 0.f); pt1 += u * w0; pr1 += u * s0;
                u = fmaxf(acc[j][3], 0.f); pt1 += u * w1; pr1 += u * s1;
            }
            pt0 += __shfl_xor_sync(0xffffffffu, pt0, 1);
            pt0 += __shfl_xor_sync(0xffffffffu, pt0, 2);
            pr0 += __shfl_xor_sync(0xffffffffu, pr0, 1);
            pr0 += __shfl_xor_sync(0xffffffffu, pr0, 2);
            pt1 += __shfl_xor_sync(0xffffffffu, pt1, 1);
            pt1 += __shfl_xor_sync(0xffffffffu, pt1, 2);
            pr1 += __shfl_xor_sync(0xffffffffu, pr1, 1);
            pr1 += __shfl_xor_sync(0xffffffffu, pr1, 2);
            float bb = __ldg(&b4[0]);
            if (q == 0) {
                if (n0 < N_NODES) { g_t[n0] = pt0; g_r[n0] = pr0 + bb; }
                if (n1 < N_NODES) { g_t[n1] = pt1; g_r[n1] = pr1 + bb; }
            }
        } else {
#pragma unroll
            for (int j = 0; j < 8; j++) {
                int c = j * 8 + 2 * q;
                if (n0 < N_NODES)
                    *(float2*)(hout + (size_t)n0 * 64 + c) =
                        make_float2(fmaxf(acc[j][0], 0.f), fmaxf(acc[j][1], 0.f));
                if (n1 < N_NODES)
                    *(float2*)(hout + (size_t)n1 * 64 + c) =
                        make_float2(fmaxf(acc[j][2], 0.f), fmaxf(acc[j][3], 0.f));
            }
        }
        __syncthreads();   // protect smem A before next tile restage
    }
}

// ---------------- the megakernel ----------------
__global__ __launch_bounds__(256, 2) void k_mega(
    const float* __restrict__ x,
    const int* __restrict__ src, const int* __restrict__ dst,
    const float* __restrict__ ew,
    const float* __restrict__ Wrel0, const float* __restrict__ brel0, const float* __restrict__ Wroot0,
    const float* __restrict__ Wrel1, const float* __restrict__ brel1, const float* __restrict__ Wroot1,
    const float* __restrict__ Wrel2, const float* __restrict__ brel2, const float* __restrict__ Wroot2,
    const float* __restrict__ Wrel3, const float* __restrict__ brel3, const float* __restrict__ Wroot3,
    const float* __restrict__ Wrel4, const float* __restrict__ brel4, const float* __restrict__ Wroot4,
    float* __restrict__ out) {
    extern __shared__ unsigned smem_u[];
    __shared__ int s_ws[8];
    __shared__ int s_bcast;
    int tid = threadIdx.x, lane = tid & 31, wid = tid >> 5;
    int bid = blockIdx.x, nb = gridDim.x;
    int gthreads = nb * 256;
    int gwarps = nb * 8;
    int gw0 = bid * 8 + wid;

    // ---- P0: pad x to 16 + histogram of dst ----
    for (int i = bid * 256 + tid; i < N_NODES * 4; i += gthreads) {
        int node = i >> 2, c = (i & 3) * 4;
        float4 v;
        v.x = (c + 0 < 13) ? __ldg(&x[node * 13 + c + 0]) : 0.f;
        v.y = (c + 1 < 13) ? __ldg(&x[node * 13 + c + 1]) : 0.f;
        v.z = (c + 2 < 13) ? __ldg(&x[node * 13 + c + 2]) : 0.f;
        v.w = (c + 3 < 13) ? __ldg(&x[node * 13 + c + 3]) : 0.f;
        ((float4*)g_x16)[i] = v;
    }
    for (int e2 = bid * 256 + tid; e2 < N_EDGES / 2; e2 += gthreads) {
        int2 d = __ldg((const int2*)dst + e2);
        atomicAdd(&g_counts[d.x], 1);
        atomicAdd(&g_counts[d.y], 1);
    }
    grid_bar();

    // ---- P1: per-block segment sums ----
    int seg = (N_NODES + nb - 1) / nb;
    int s0 = bid * seg;
    int s1 = min(s0 + seg, N_NODES);
    {
        int sum = 0;
        for (int i = s0 + tid; i < s1; i += 256) sum += __ldcg(&g_counts[i]);
#pragma unroll
        for (int o = 16; o > 0; o >>= 1) sum += __shfl_xor_sync(0xffffffffu, sum, o);
        if (lane == 0) s_ws[wid] = sum;
        __syncthreads();
        if (tid == 0) {
            int t = 0;
            for (int j = 0; j < 8; j++) t += s_ws[j];
            g_bsum[bid] = t;
        }
        __syncthreads();
    }
    grid_bar();

    // ---- P2: rowptr/cursor (prefix), restore counts=0 ----
    {
        int base = 0;
        for (int j = tid; j < bid; j += 256) base += __ldcg(&g_bsum[j]);
#pragma unroll
        for (int o = 16; o > 0; o >>= 1) base += __shfl_xor_sync(0xffffffffu, base, o);
        if (lane == 0) s_ws[wid] = base;
        __syncthreads();
        if (tid == 0) {
            int t = 0;
            for (int j = 0; j < 8; j++) t += s_ws[j];
            s_bcast = t;
        }
        __syncthreads();
        base = s_bcast;
        __syncthreads();

        int carry = 0;
        for (int c = s0; c < s1; c += 256) {
            int i = c + tid;
            int v = (i < s1) ? __ldcg(&g_counts[i]) : 0;
            int sv = v;
#pragma unroll
            for (int o = 1; o < 32; o <<= 1) {
                int t = __shfl_up_sync(0xffffffffu, sv, o);
                if (lane >= o) sv += t;
            }
            if (lane == 31) s_ws[wid] = sv;
            __syncthreads();
            if (wid == 0) {
                int w8 = (lane < 8) ? s_ws[lane] : 0;
#pragma unroll
                for (int o = 1; o < 8; o <<= 1) {
                    int t = __shfl_up_sync(0xffffffffu, w8, o);
                    if (lane >= o) w8 += t;
                }
                if (lane < 8) s_ws[lane] = w8;
            }
            __syncthreads();
            int add = (wid > 0) ? s_ws[wid - 1] : 0;
            int total = s_ws[7];
            if (i < s1) {
                int excl = base + carry + sv + add - v;
                g_rowptr[i] = excl;
                g_cursor[i] = excl;
                g_counts[i] = 0;                 // restore invariant
                if (i == N_NODES - 1) g_rowptr[N_NODES] = excl + v;
            }
            carry += total;
            __syncthreads();
        }
    }
    grid_bar();

    // ---- P3: scatter edges into CSR order ----
    for (int e2 = bid * 256 + tid; e2 < N_EDGES / 2; e2 += gthreads) {
        int2 s = __ldg((const int2*)src + e2);
        int2 d = __ldg((const int2*)dst + e2);
        float2 w = __ldg((const float2*)ew + e2);
        int p0 = atomicAdd(&g_cursor[d.x], 1);
        g_edge[p0] = make_int2(s.x, __float_as_int(w.x));
        int p1 = atomicAdd(&g_cursor[d.y], 1);
        g_edge[p1] = make_int2(s.y, __float_as_int(w.y));
    }
    grid_bar();

    // ---- P4: layer-0 aggregation (13-dim over padded x16) ----
    {
        int grp = lane >> 2, sl4 = lane & 3;
        const float4* __restrict__ x4 = (const float4*)g_x16;
        for (int w = gw0; w < N_NODES; w += gwarps) {
            int i = __ldcg(&g_rowptr[w]) + grp, e = __ldcg(&g_rowptr[w + 1]);
            float4 a = make_float4(0.f, 0.f, 0.f, 0.f);
            for (; i < e; i += 8) {
                int2 m = __ldcg(&g_edge[i]);
                float4 v = __ldcg(x4 + m.x * 4 + sl4);
                float ww = __int_as_float(m.y);
                a.x += ww * v.x; a.y += ww * v.y; a.z += ww * v.z; a.w += ww * v.w;
            }
#pragma unroll
            for (int o = 4; o < 32; o <<= 1) {
                a.x += __shfl_xor_sync(0xffffffffu, a.x, o);
                a.y += __shfl_xor_sync(0xffffffffu, a.y, o);
                a.z += __shfl_xor_sync(0xffffffffu, a.z, o);
                a.w += __shfl_xor_sync(0xffffffffu, a.w, o);
            }
            if (grp == 0) ((float4*)(g_aggr + (size_t)w * 16))[sl4] = a;
        }
    }
    grid_bar();

    // ---- P5: GEMM 13->64 (FFMA) ----
    {
        float* sW = (float*)smem_u;            // 2*13*64 floats
        float* sb = sW + 2 * 13 * 64;          // 64
        for (int idx = tid; idx < 13 * 64; idx += 256) {
            sW[idx]           = __ldg(&Wrel0[idx]);
            sW[13 * 64 + idx] = __ldg(&Wroot0[idx]);
        }
        if (tid < 64) sb[tid] = __ldg(&brel0[tid]);
        __syncthreads();
        const float4* sWrel4  = (const float4*)sW;
        const float4* sWroot4 = (const float4*)(sW + 13 * 64);
        int cq = (tid & 3) * 4, c0 = cq * 4;
        for (int t = bid; t < NT13; t += nb) {
            int node = t * 64 + (tid >> 2);
            if (node < N_NODES) {
                float acc[16];
#pragma unroll
                for (int j = 0; j < 16; j++) acc[j] = sb[c0 + j];
#pragma unroll
                for (int k = 0; k < 13; k++) {
                    float a  = __ldcg(&g_aggr[node * 16 + k]);
                    float hk = __ldg(&x[node * 13 + k]);
#pragma unroll
                    for (int j = 0; j < 4; j++) {
                        float4 wr = sWrel4[k * 16 + cq + j];
                        float4 ws = sWroot4[k * 16 + cq + j];
                        acc[4 * j + 0] += a * wr.x + hk * ws.x;
                        acc[4 * j + 1] += a * wr.y + hk * ws.y;
                        acc[4 * j + 2] += a * wr.z + hk * ws.z;
                        acc[4 * j + 3] += a * wr.w + hk * ws.w;
                    }
                }
                float4* o4 = (float4*)(g_h[0] + (size_t)node * 64 + c0);
#pragma unroll
                for (int j = 0; j < 4; j++) {
                    float4 v;
                    v.x = fmaxf(acc[4 * j + 0], 0.f); v.y = fmaxf(acc[4 * j + 1], 0.f);
                    v.z = fmaxf(acc[4 * j + 2], 0.f); v.w = fmaxf(acc[4 * j + 3], 0.f);
                    o4[j] = v;
                }
            }
        }
    }
    grid_bar();

    // ---- layers 1..3 ----
    phase_aggr64(g_h[0], gw0, gwarps);
    grid_bar();
    phase_gemm64(g_h[0], g_h[1], Wrel1, brel1, Wroot1, 0, 0, 0, false, smem_u);
    grid_bar();
    phase_aggr64(g_h[1], gw0, gwarps);
    grid_bar();
    phase_gemm64(g_h[1], g_h[0], Wrel2, brel2, Wroot2, 0, 0, 0, false, smem_u);
    grid_bar();
    phase_aggr64(g_h[0], gw0, gwarps);
    grid_bar();
    phase_gemm64(g_h[0], 0, Wrel3, brel3, Wroot3, Wrel4, brel4, Wroot4, true, smem_u);
    grid_bar();

    // ---- P12: final scalar aggregation + sigmoid ----
    for (int w = gw0; w < N_NODES; w += gwarps) {
        int start = __ldcg(&g_rowptr[w]), end = __ldcg(&g_rowptr[w + 1]);
        float acc = 0.f;
        for (int e = start + lane; e < end; e += 32) {
            int2 er = __ldcg(&g_edge[e]);
            acc += __int_as_float(er.y) * __ldcg(&g_t[er.x]);
        }
#pragma unroll
        for (int o = 16; o > 0; o >>= 1)
            acc += __shfl_xor_sync(0xffffffffu, acc, o);
        if (lane == 0) {
            float z = acc + __ldcg(&g_r[w]);
            out[w] = 1.f / (1.f + expf(-z));
        }
    }
}

// ---------------- launch ----------------
extern "C" void kernel_launch(void* const* d_in, const int* in_sizes, int n_in,
                              void* d_out, int out_size) {
    const float* x  = (const float*)d_in[0];
    const int*   ei = (const int*)d_in[1];
    const float* ew = (const float*)d_in[2];
    const int* src = ei;
    const int* dst = ei + N_EDGES;

    const float* W[15];
    for (int i = 0; i < 15; i++) W[i] = (const float*)d_in[3 + i];
    float* out = (float*)d_out;

    cudaFuncSetAttribute(k_mega, cudaFuncAttributeMaxDynamicSharedMemorySize, SMEM_BYTES);

    int dev = 0, sms = 148, occ = 1;
    cudaGetDevice(&dev);
    cudaDeviceGetAttribute(&sms, cudaDevAttrMultiProcessorCount, dev);
    cudaOccupancyMaxActiveBlocksPerMultiprocessor(&occ, k_mega, 256, SMEM_BYTES);
    if (occ < 1) occ = 1;
    int blocks = sms * occ;
    if (blocks > 1024) blocks = 1024;

    k_mega<<<blocks, 256, SMEM_BYTES>>>(
        x, src, dst, ew,
        W[0], W[1], W[2],
        W[3], W[4], W[5],
        W[6], W[7], W[8],
        W[9], W[10], W[11],
        W[12], W[13], W[14],
        out);
}

// round 8
// speedup vs baseline: 1.2718x; 1.2718x over previous
#include <cuda_runtime.h>
#include <math.h>

#define N_NODES 50000
#define N_EDGES 800000
#define SCAN_B  1024
#define SCAN_NB ((N_NODES + SCAN_B - 1) / SCAN_B)   // 49

// griddepcontrol (PDL)
#define PDL_TRIGGER() asm volatile("griddepcontrol.launch_dependents;" ::: "memory")
#define PDL_WAIT()    asm volatile("griddepcontrol.wait;" ::: "memory")

// ---------------- scratch (static device memory; no allocs) ----------------
__device__ int      g_counts[N_NODES];     // invariant: zero at kernel_launch entry
__device__ int      g_rowptr[N_NODES + 1];
__device__ int      g_cursor[N_NODES];
__device__ int      g_tmp[N_NODES];
__device__ int      g_bsum[SCAN_NB];
__device__ int2     g_edge[N_EDGES];       // {src, weight-as-int}
__device__ float    g_x16[N_NODES * 16];   // x padded 13 -> 16
__device__ float    g_h[2][N_NODES * 64];  // fp32 h (GEMM root path)
__device__ unsigned g_hbf[2][N_NODES * 32];// bf16x2 mirror of h (aggr gather path)
__device__ float    g_aggr[N_NODES * 64];  // fp32 aggregates (also 16-stride layer0)
__device__ float    g_t[N_NODES];
__device__ float    g_r[N_NODES];

// ---------------- helpers ----------------
__device__ __forceinline__ unsigned bf16_rn(float f) {
    unsigned u = __float_as_uint(f);
    return (u + 0x7fffu + ((u >> 16) & 1u)) >> 16;
}
__device__ __forceinline__ unsigned pack_bf2(float d0, float d1) {
    return bf16_rn(d0) | (bf16_rn(d1) << 16);
}
__device__ __forceinline__ float bf_lo(unsigned u) { return __uint_as_float(u << 16); }
__device__ __forceinline__ float bf_hi(unsigned u) { return __uint_as_float(u & 0xffff0000u); }

__device__ __forceinline__ void mma_bf16(float* c,
                                         unsigned a0, unsigned a1, unsigned a2, unsigned a3,
                                         unsigned b0, unsigned b1) {
    asm volatile(
        "mma.sync.aligned.m16n8k16.row.col.f32.bf16.bf16.f32 "
        "{%0,%1,%2,%3}, {%4,%5,%6,%7}, {%8,%9}, {%0,%1,%2,%3};\n"
        : "+f"(c[0]), "+f"(c[1]), "+f"(c[2]), "+f"(c[3])
        : "r"(a0), "r"(a1), "r"(a2), "r"(a3), "r"(b0), "r"(b1));
}

// ---------------- CSR build (padx merged into hist) ------------------------
__global__ void k_hist(const int* __restrict__ dst, const float* __restrict__ x) {
    PDL_TRIGGER();
    int gt = blockIdx.x * blockDim.x + threadIdx.x;
    int gs = gridDim.x * blockDim.x;
    // pad x -> x16 (input-only, pre-wait safe)
    for (int i = gt; i < N_NODES * 4; i += gs) {
        int node = i >> 2, c = (i & 3) * 4;
        float4 v;
        v.x = (c + 0 < 13) ? __ldg(&x[node * 13 + c + 0]) : 0.f;
        v.y = (c + 1 < 13) ? __ldg(&x[node * 13 + c + 1]) : 0.f;
        v.z = (c + 2 < 13) ? __ldg(&x[node * 13 + c + 2]) : 0.f;
        v.w = (c + 3 < 13) ? __ldg(&x[node * 13 + c + 3]) : 0.f;
        ((float4*)g_x16)[i] = v;
    }
    int e2 = gt;
    int2 d = make_int2(0, 0);
    bool ok = (2 * e2 < N_EDGES);
    if (ok) d = __ldg((const int2*)dst + e2);
    PDL_WAIT();
    if (ok) {
        atomicAdd(&g_counts[d.x], 1);
        atomicAdd(&g_counts[d.y], 1);
    }
}

__global__ void k_scan_part() {
    PDL_TRIGGER();
    __shared__ int swarp[32];
    int tid = threadIdx.x, lane = tid & 31, wid = tid >> 5;
    int i = blockIdx.x * SCAN_B + tid;
    PDL_WAIT();
    int v = (i < N_NODES) ? g_counts[i] : 0;
#pragma unroll
    for (int o = 1; o < 32; o <<= 1) {
        int t = __shfl_up_sync(0xffffffffu, v, o);
        if (lane >= o) v += t;
    }
    if (lane == 31) swarp[wid] = v;
    __syncthreads();
    if (wid == 0) {
        int w = swarp[lane];
#pragma unroll
        for (int o = 1; o < 32; o <<= 1) {
            int t = __shfl_up_sync(0xffffffffu, w, o);
            if (lane >= o) w += t;
        }
        swarp[lane] = w;
    }
    __syncthreads();
    if (wid > 0) v += swarp[wid - 1];
    if (i < N_NODES) g_tmp[i] = v;
    if (tid == SCAN_B - 1) g_bsum[blockIdx.x] = v;
}

__global__ void k_scan_fin() {
    PDL_TRIGGER();
    __shared__ int soff;
    int tid = threadIdx.x;
    PDL_WAIT();
    if (tid < 32) {
        int v = 0;
        for (int j = tid; j < (int)blockIdx.x; j += 32) v += g_bsum[j];
#pragma unroll
        for (int o = 16; o > 0; o >>= 1) v += __shfl_xor_sync(0xffffffffu, v, o);
        if (tid == 0) soff = v;
    }
    __syncthreads();
    int off = soff;
    int i = blockIdx.x * SCAN_B + tid;
    if (i < N_NODES) {
        int incl = g_tmp[i] + off;
        int c = g_counts[i];
        int excl = incl - c;
        g_rowptr[i] = excl;
        g_cursor[i] = excl;
        g_counts[i] = 0;                 // restore invariant for next replay
        if (i == N_NODES - 1) g_rowptr[N_NODES] = incl;
    }
}

__global__ void k_scatter(const int* __restrict__ src, const int* __restrict__ dst,
                          const float* __restrict__ ew) {
    PDL_TRIGGER();
    int e2 = blockIdx.x * blockDim.x + threadIdx.x;
    bool ok = (2 * e2 < N_EDGES);
    int2 s = make_int2(0, 0), d = make_int2(0, 0);
    float2 w = make_float2(0.f, 0.f);
    if (ok) {
        s = __ldg((const int2*)src + e2);
        d = __ldg((const int2*)dst + e2);
        w = __ldg((const float2*)ew + e2);
    }
    PDL_WAIT();
    if (ok) {
        int p0 = atomicAdd(&g_cursor[d.x], 1);
        g_edge[p0] = make_int2(s.x, __float_as_int(w.x));
        int p1 = atomicAdd(&g_cursor[d.y], 1);
        g_edge[p1] = make_int2(s.y, __float_as_int(w.y));
    }
}

// ---------------- aggregation: warp per node over bf16 rows ----------------
// One 128B line per edge. lane l covers dims (2l, 2l+1). fp32 accumulate.
__global__ void k_aggr64(int sel) {
    PDL_TRIGGER();
    PDL_WAIT();
    int w = (blockIdx.x * blockDim.x + threadIdx.x) >> 5;
    if (w >= N_NODES) return;
    int lane = threadIdx.x & 31;
    const unsigned* __restrict__ hb = g_hbf[sel];
    int i = g_rowptr[w], e = g_rowptr[w + 1];
    float a0x = 0.f, a0y = 0.f, a1x = 0.f, a1y = 0.f;
    float a2x = 0.f, a2y = 0.f, a3x = 0.f, a3y = 0.f;
    for (; i + 4 <= e; i += 4) {
        int2 m0 = __ldg(&g_edge[i + 0]);
        int2 m1 = __ldg(&g_edge[i + 1]);
        int2 m2 = __ldg(&g_edge[i + 2]);
        int2 m3 = __ldg(&g_edge[i + 3]);
        unsigned u0 = __ldg(&hb[m0.x * 32 + lane]);
        unsigned u1 = __ldg(&hb[m1.x * 32 + lane]);
        unsigned u2 = __ldg(&hb[m2.x * 32 + lane]);
        unsigned u3 = __ldg(&hb[m3.x * 32 + lane]);
        float w0 = __int_as_float(m0.y), w1 = __int_as_float(m1.y);
        float w2 = __int_as_float(m2.y), w3 = __int_as_float(m3.y);
        a0x += w0 * bf_lo(u0); a0y += w0 * bf_hi(u0);
        a1x += w1 * bf_lo(u1); a1y += w1 * bf_hi(u1);
        a2x += w2 * bf_lo(u2); a2y += w2 * bf_hi(u2);
        a3x += w3 * bf_lo(u3); a3y += w3 * bf_hi(u3);
    }
    for (; i < e; i++) {
        int2 m = __ldg(&g_edge[i]);
        unsigned u = __ldg(&hb[m.x * 32 + lane]);
        float ww = __int_as_float(m.y);
        a0x += ww * bf_lo(u); a0y += ww * bf_hi(u);
    }
    float2 o;
    o.x = a0x + a1x + a2x + a3x;
    o.y = a0y + a1y + a2y + a3y;
    *((float2*)(g_aggr + (size_t)w * 64) + lane) = o;
}

// layer 0: warp per node, 8 edge-slots x 4 lanes x float4 over padded x16
__global__ void k_aggr13() {
    PDL_TRIGGER();
    PDL_WAIT();
    int w = (blockIdx.x * blockDim.x + threadIdx.x) >> 5;
    if (w >= N_NODES) return;
    int lane = threadIdx.x & 31, grp = lane >> 2, sl = lane & 3;
    const float4* __restrict__ x4 = (const float4*)g_x16;
    int i = g_rowptr[w] + grp, e = g_rowptr[w + 1];
    float4 a = make_float4(0.f, 0.f, 0.f, 0.f);
    for (; i < e; i += 8) {
        int2 r = __ldg(&g_edge[i]);
        float4 v = __ldg(x4 + r.x * 4 + sl);
        float ww = __int_as_float(r.y);
        a.x += ww * v.x; a.y += ww * v.y; a.z += ww * v.z; a.w += ww * v.w;
    }
#pragma unroll
    for (int o = 4; o < 32; o <<= 1) {
        a.x += __shfl_xor_sync(0xffffffffu, a.x, o);
        a.y += __shfl_xor_sync(0xffffffffu, a.y, o);
        a.z += __shfl_xor_sync(0xffffffffu, a.z, o);
        a.w += __shfl_xor_sync(0xffffffffu, a.w, o);
    }
    if (grp == 0) ((float4*)(g_aggr + (size_t)w * 16))[sl] = a;
}

// ---------------- GEMM 13->64 (FFMA; writes fp32 h + bf16 mirror) ----------
__global__ __launch_bounds__(256) void k_gemm13(
    const float* __restrict__ x,
    const float* __restrict__ Wrel, const float* __restrict__ brel,
    const float* __restrict__ Wroot) {
    PDL_TRIGGER();
    __shared__ __align__(16) float sW[2 * 13 * 64];
    __shared__ float sb[64];
    int tid = threadIdx.x;
    for (int idx = tid; idx < 13 * 64; idx += 256) {
        sW[idx]           = Wrel[idx];
        sW[13 * 64 + idx] = Wroot[idx];
    }
    if (tid < 64) sb[tid] = brel[tid];
    PDL_WAIT();
    __syncthreads();

    int node = blockIdx.x * 64 + (tid >> 2);
    int cq   = (tid & 3) * 4;
    int c0   = cq * 4;
    if (node >= N_NODES) return;
    float acc[16];
#pragma unroll
    for (int j = 0; j < 16; j++) acc[j] = sb[c0 + j];
    const float4* sWrel4  = (const float4*)sW;
    const float4* sWroot4 = (const float4*)(sW + 13 * 64);
#pragma unroll
    for (int k = 0; k < 13; k++) {
        float a  = __ldg(&g_aggr[node * 16 + k]);
        float hk = __ldg(&x[node * 13 + k]);
#pragma unroll
        for (int j = 0; j < 4; j++) {
            float4 wr = sWrel4[k * 16 + cq + j];
            float4 ws = sWroot4[k * 16 + cq + j];
            acc[4 * j + 0] += a * wr.x + hk * ws.x;
            acc[4 * j + 1] += a * wr.y + hk * ws.y;
            acc[4 * j + 2] += a * wr.z + hk * ws.z;
            acc[4 * j + 3] += a * wr.w + hk * ws.w;
        }
    }
    float4* o4 = (float4*)(g_h[0] + (size_t)node * 64 + c0);
    unsigned* ob = g_hbf[0] + (size_t)node * 32 + (c0 >> 1);
#pragma unroll
    for (int j = 0; j < 4; j++) {
        float4 v;
        v.x = fmaxf(acc[4 * j + 0], 0.f); v.y = fmaxf(acc[4 * j + 1], 0.f);
        v.z = fmaxf(acc[4 * j + 2], 0.f); v.w = fmaxf(acc[4 * j + 3], 0.f);
        o4[j] = v;
        ob[2 * j]     = pack_bf2(v.x, v.y);
        ob[2 * j + 1] = pack_bf2(v.z, v.w);
    }
}

// ---------------- GEMM 64->64 via bf16 3-term MMA --------------------------
#define AW 68   // padded word stride (bank-conflict-free)
template <bool FINAL>
__global__ __launch_bounds__(256) void k_gemm64_mma(
    const float* __restrict__ Wrel, const float* __restrict__ brel,
    const float* __restrict__ Wroot,
    const float* __restrict__ Wrel4, const float* __restrict__ b4,
    const float* __restrict__ Wroot4,
    int insel, int outsel) {
    PDL_TRIGGER();
    extern __shared__ unsigned smem_u[];
    unsigned* sAhi = smem_u;                    // 128*AW
    unsigned* sAlo = sAhi + 128 * AW;           // 128*AW
    unsigned* sWhi = sAlo + 128 * AW;           // 64*AW
    unsigned* sWlo = sWhi + 64 * AW;            // 64*AW
    float*    sb   = (float*)(sWlo + 64 * AW);  // 64

    int tid = threadIdx.x;
    const float* __restrict__ hin = g_h[insel];
    int nbase = blockIdx.x * 128;

    if (tid < 64) sb[tid] = brel[tid];

    for (int p = tid; p < 64 * 64; p += 256) {    // harness inputs: pre-wait
        int col = p >> 6, w = p & 63;
        int k = 2 * w;
        float f0, f1;
        if (k < 64) { f0 = __ldg(&Wrel[k * 64 + col]);         f1 = __ldg(&Wrel[(k + 1) * 64 + col]); }
        else        { f0 = __ldg(&Wroot[(k - 64) * 64 + col]); f1 = __ldg(&Wroot[(k - 63) * 64 + col]); }
        unsigned h0 = bf16_rn(f0), h1 = bf16_rn(f1);
        sWhi[col * AW + w] = h0 | (h1 << 16);
        sWlo[col * AW + w] = bf16_rn(f0 - __uint_as_float(h0 << 16)) |
                             (bf16_rn(f1 - __uint_as_float(h1 << 16)) << 16);
    }
    PDL_WAIT();
    for (int p = tid; p < 128 * 32; p += 256) {
        int ln = p >> 5, w = p & 31;
        int node = nbase + ln;
        if (node >= N_NODES) node = N_NODES - 1;
        float2 va = *(const float2*)(g_aggr + (size_t)node * 64 + 2 * w);
        float2 vh = *(const float2*)(hin    + (size_t)node * 64 + 2 * w);
        {
            unsigned h0 = bf16_rn(va.x), h1 = bf16_rn(va.y);
            sAhi[ln * AW + w] = h0 | (h1 << 16);
            sAlo[ln * AW + w] = bf16_rn(va.x - __uint_as_float(h0 << 16)) |
                                (bf16_rn(va.y - __uint_as_float(h1 << 16)) << 16);
        }
        {
            unsigned h0 = bf16_rn(vh.x), h1 = bf16_rn(vh.y);
            sAhi[ln * AW + 32 + w] = h0 | (h1 << 16);
            sAlo[ln * AW + 32 + w] = bf16_rn(vh.x - __uint_as_float(h0 << 16)) |
                                     (bf16_rn(vh.y - __uint_as_float(h1 << 16)) << 16);
        }
    }
    __syncthreads();

    int warp = tid >> 5, lane = tid & 31;
    int r = lane >> 2, q = lane & 3;
    int mb = warp * 16;

    float acc[8][4];
#pragma unroll
    for (int j = 0; j < 8; j++) {
        float b0 = sb[j * 8 + 2 * q], b1 = sb[j * 8 + 2 * q + 1];
        acc[j][0] = b0; acc[j][1] = b1; acc[j][2] = b0; acc[j][3] = b1;
    }

    int arow0 = (mb + r) * AW, arow1 = (mb + r + 8) * AW;
#pragma unroll
    for (int ks = 0; ks < 8; ks++) {
        int kw = ks * 8 + q;
        unsigned ah0 = sAhi[arow0 + kw],     ah1 = sAhi[arow1 + kw];
        unsigned ah2 = sAhi[arow0 + kw + 4], ah3 = sAhi[arow1 + kw + 4];
        unsigned al0 = sAlo[arow0 + kw],     al1 = sAlo[arow1 + kw];
        unsigned al2 = sAlo[arow0 + kw + 4], al3 = sAlo[arow1 + kw + 4];
#pragma unroll
        for (int j = 0; j < 8; j++) {
            int brow = (j * 8 + r) * AW + ks * 8 + q;
            unsigned bh0 = sWhi[brow], bh1 = sWhi[brow + 4];
            unsigned bl0 = sWlo[brow], bl1 = sWlo[brow + 4];
            mma_bf16(acc[j], ah0, ah1, ah2, ah3, bh0, bh1);
            mma_bf16(acc[j], ah0, ah1, ah2, ah3, bl0, bl1);
            mma_bf16(acc[j], al0, al1, al2, al3, bh0, bh1);
        }
    }

    int n0 = nbase + mb + r;      // row of c0/c1
    int n1 = n0 + 8;              // row of c2/c3
    if (FINAL) {
        float pt0 = 0.f, pr0 = 0.f, pt1 = 0.f, pr1 = 0.f;
#pragma unroll
        for (int j = 0; j < 8; j++) {
            int c = j * 8 + 2 * q;
            float w0 = __ldg(&Wrel4[c]),  w1 = __ldg(&Wrel4[c + 1]);
            float s0 = __ldg(&Wroot4[c]), s1 = __ldg(&Wroot4[c + 1]);
            float u;
            u = fmaxf(acc[j][0], 0.f); pt0 += u * w0; pr0 += u * s0;
            u = fmaxf(acc[j][1], 0.f); pt0 += u * w1; pr0 += u * s1;
            u = fmaxf(acc[j][2], 0.f); pt1 += u * w0; pr1 += u * s0;
            u = fmaxf(acc[j][3], 0.f); pt1 += u * w1; pr1 += u * s1;
        }
        pt0 += __shfl_xor_sync(0xffffffffu, pt0, 1);
        pt0 += __shfl_xor_sync(0xffffffffu, pt0, 2);
        pr0 += __shfl_xor_sync(0xffffffffu, pr0, 1);
        pr0 += __shfl_xor_sync(0xffffffffu, pr0, 2);
        pt1 += __shfl_xor_sync(0xffffffffu, pt1, 1);
        pt1 += __shfl_xor_sync(0xffffffffu, pt1, 2);
        pr1 += __shfl_xor_sync(0xffffffffu, pr1, 1);
        pr1 += __shfl_xor_sync(0xffffffffu, pr1, 2);
        float bb = __ldg(&b4[0]);
        if (q == 0) {
            if (n0 < N_NODES) { g_t[n0] = pt0; g_r[n0] = pr0 + bb; }
            if (n1 < N_NODES) { g_t[n1] = pt1; g_r[n1] = pr1 + bb; }
        }
    } else {
        float* ob = g_h[outsel];
        unsigned* obf = g_hbf[outsel];
#pragma unroll
        for (int j = 0; j < 8; j++) {
            int c = j * 8 + 2 * q;
            if (n0 < N_NODES) {
                float v0 = fmaxf(acc[j][0], 0.f), v1 = fmaxf(acc[j][1], 0.f);
                *(float2*)(ob + (size_t)n0 * 64 + c) = make_float2(v0, v1);
                obf[(size_t)n0 * 32 + (c >> 1)] = pack_bf2(v0, v1);
            }
            if (n1 < N_NODES) {
                float v0 = fmaxf(acc[j][2], 0.f), v1 = fmaxf(acc[j][3], 0.f);
                *(float2*)(ob + (size_t)n1 * 64 + c) = make_float2(v0, v1);
                obf[(size_t)n1 * 32 + (c >> 1)] = pack_bf2(v0, v1);
            }
        }
    }
}

// ---------------- final: out = sigmoid(segsum(w * t[src]) + r) -------------
__global__ void k_final(float* __restrict__ out) {
    PDL_TRIGGER();
    PDL_WAIT();
    int gw   = (blockIdx.x * blockDim.x + threadIdx.x) >> 5;
    int lane = threadIdx.x & 31;
    if (gw >= N_NODES) return;
    int start = g_rowptr[gw], end = g_rowptr[gw + 1];
    float acc = 0.f;
    for (int e = start + lane; e < end; e += 32) {
        int2 er = __ldg(&g_edge[e]);
        acc += __int_as_float(er.y) * __ldg(&g_t[er.x]);
    }
#pragma unroll
    for (int o = 16; o > 0; o >>= 1)
        acc += __shfl_xor_sync(0xffffffffu, acc, o);
    if (lane == 0) {
        float z = acc + g_r[gw];
        out[gw] = 1.f / (1.f + expf(-z));
    }
}

// ---------------- launch helpers ----------------
template <typename F, typename... Args>
static void launch_pdl(F f, dim3 g, dim3 b, size_t sm, Args... args) {
    cudaLaunchConfig_t cfg = {};
    cfg.gridDim = g;
    cfg.blockDim = b;
    cfg.dynamicSmemBytes = sm;
    cfg.stream = 0;
    cudaLaunchAttribute at[1];
    at[0].id = cudaLaunchAttributeProgrammaticStreamSerialization;
    at[0].val.programmaticStreamSerializationAllowed = 1;
    cfg.attrs = at;
    cfg.numAttrs = 1;
    cudaLaunchKernelEx(&cfg, f, args...);
}

extern "C" void kernel_launch(void* const* d_in, const int* in_sizes, int n_in,
                              void* d_out, int out_size) {
    const float* x  = (const float*)d_in[0];
    const int*   ei = (const int*)d_in[1];
    const float* ew = (const float*)d_in[2];
    const int* src = ei;
    const int* dst = ei + N_EDGES;

    const float* Wrel[5], * brel[5], * Wroot[5];
    for (int l = 0; l < 5; l++) {
        Wrel[l]  = (const float*)d_in[3 + 3 * l];
        brel[l]  = (const float*)d_in[4 + 3 * l];
        Wroot[l] = (const float*)d_in[5 + 3 * l];
    }
    float* out = (float*)d_out;

    const int SMEM_MMA = (128 * AW * 2 + 64 * AW * 2 + 64) * 4;   // 104704 B
    cudaFuncSetAttribute(k_gemm64_mma<false>,
                         cudaFuncAttributeMaxDynamicSharedMemorySize, SMEM_MMA);
    cudaFuncSetAttribute(k_gemm64_mma<true>,
                         cudaFuncAttributeMaxDynamicSharedMemorySize, SMEM_MMA);

    const int TB = 256;
    dim3 B(TB);
    int gE2  = (N_EDGES / 2 + TB - 1) / TB;       // 2 edges/thread (covers padx too)
    int gW   = (N_NODES * 32 + TB - 1) / TB;      // warp-per-node
    int g64  = (N_NODES + 63) / 64;
    int g128 = (N_NODES + 127) / 128;

    // CSR build (g_counts zero by invariant); padx folded into k_hist
    launch_pdl(k_hist, dim3(gE2), B, 0, dst, x);
    launch_pdl(k_scan_part, dim3(SCAN_NB), dim3(SCAN_B), 0);
    launch_pdl(k_scan_fin,  dim3(SCAN_NB), dim3(SCAN_B), 0);
    launch_pdl(k_scatter, dim3(gE2), B, 0, src, dst, ew);

    // layer 0: 13 -> 64
    launch_pdl(k_aggr13, dim3(gW), B, 0);
    launch_pdl(k_gemm13, dim3(g64), B, 0, x, Wrel[0], brel[0], Wroot[0]);

    // layers 1-3: 64 -> 64 (layer 3 folds the 64->1 projection of layer 4)
    launch_pdl(k_aggr64, dim3(gW), B, 0, 0);
    launch_pdl(k_gemm64_mma<false>, dim3(g128), B, (size_t)SMEM_MMA,
               Wrel[1], brel[1], Wroot[1],
               (const float*)nullptr, (const float*)nullptr, (const float*)nullptr, 0, 1);
    launch_pdl(k_aggr64, dim3(gW), B, 0, 1);
    launch_pdl(k_gemm64_mma<false>, dim3(g128), B, (size_t)SMEM_MMA,
               Wrel[2], brel[2], Wroot[2],
               (const float*)nullptr, (const float*)nullptr, (const float*)nullptr, 1, 0);
    launch_pdl(k_aggr64, dim3(gW), B, 0, 0);
    launch_pdl(k_gemm64_mma<true>, dim3(g128), B, (size_t)SMEM_MMA,
               Wrel[3], brel[3], Wroot[3],
               Wrel[4], brel[4], Wroot[4], 0, 0);

    // layer 4 aggregation (scalar) + sigmoid
    launch_pdl(k_final, dim3(gW), B, 0, out);
}

// round 9
// speedup vs baseline: 1.3805x; 1.0854x over previous
#include <cuda_runtime.h>
#include <math.h>

#define N_NODES 50000
#define N_EDGES 800000
#define SCAN_B  1024
#define SCAN_NB ((N_NODES + SCAN_B - 1) / SCAN_B)   // 49

// griddepcontrol (PDL)
#define PDL_TRIGGER() asm volatile("griddepcontrol.launch_dependents;" ::: "memory")
#define PDL_WAIT()    asm volatile("griddepcontrol.wait;" ::: "memory")

// ---------------- scratch (static device memory; no allocs) ----------------
__device__ int   g_counts[N_NODES];        // invariant: zero at kernel_launch entry
__device__ int   g_rowptr[N_NODES + 1];
__device__ int   g_cursor[N_NODES];
__device__ int   g_tmp[N_NODES];
__device__ int   g_bsum[SCAN_NB];
__device__ int2  g_edge[N_EDGES];          // {src, weight-as-int}
__device__ float g_x16[N_NODES * 16];      // x padded 13 -> 16
__device__ float g_h[2][N_NODES * 64];
__device__ float g_aggr[N_NODES * 64];
__device__ float g_t[N_NODES];
__device__ float g_r[N_NODES];

// ---------------- helpers ----------------
// one-instruction pack: bits[15:0]=bf16(lo), bits[31:16]=bf16(hi), round-to-nearest-even
__device__ __forceinline__ unsigned cvt_bf2(float lo, float hi) {
    unsigned r;
    asm("cvt.rn.bf16x2.f32 %0, %1, %2;" : "=r"(r) : "f"(hi), "f"(lo));
    return r;
}
__device__ __forceinline__ float bf_lo(unsigned u) { return __uint_as_float(u << 16); }
__device__ __forceinline__ float bf_hi(unsigned u) { return __uint_as_float(u & 0xffff0000u); }

__device__ __forceinline__ void mma_bf16(float* c,
                                         unsigned a0, unsigned a1, unsigned a2, unsigned a3,
                                         unsigned b0, unsigned b1) {
    asm volatile(
        "mma.sync.aligned.m16n8k16.row.col.f32.bf16.bf16.f32 "
        "{%0,%1,%2,%3}, {%4,%5,%6,%7}, {%8,%9}, {%0,%1,%2,%3};\n"
        : "+f"(c[0]), "+f"(c[1]), "+f"(c[2]), "+f"(c[3])
        : "r"(a0), "r"(a1), "r"(a2), "r"(a3), "r"(b0), "r"(b1));
}

// ---------------- CSR build (padx merged into hist) ------------------------
__global__ void k_hist(const int* __restrict__ dst, const float* __restrict__ x) {
    PDL_TRIGGER();
    int gt = blockIdx.x * blockDim.x + threadIdx.x;
    int gs = gridDim.x * blockDim.x;
    for (int i = gt; i < N_NODES * 4; i += gs) {      // input-only: pre-wait
        int node = i >> 2, c = (i & 3) * 4;
        float4 v;
        v.x = (c + 0 < 13) ? __ldg(&x[node * 13 + c + 0]) : 0.f;
        v.y = (c + 1 < 13) ? __ldg(&x[node * 13 + c + 1]) : 0.f;
        v.z = (c + 2 < 13) ? __ldg(&x[node * 13 + c + 2]) : 0.f;
        v.w = (c + 3 < 13) ? __ldg(&x[node * 13 + c + 3]) : 0.f;
        ((float4*)g_x16)[i] = v;
    }
    int e2 = gt;
    int2 d = make_int2(0, 0);
    bool ok = (2 * e2 < N_EDGES);
    if (ok) d = __ldg((const int2*)dst + e2);
    PDL_WAIT();
    if (ok) {
        atomicAdd(&g_counts[d.x], 1);
        atomicAdd(&g_counts[d.y], 1);
    }
}

__global__ void k_scan_part() {
    PDL_TRIGGER();
    __shared__ int swarp[32];
    int tid = threadIdx.x, lane = tid & 31, wid = tid >> 5;
    int i = blockIdx.x * SCAN_B + tid;
    PDL_WAIT();
    int v = (i < N_NODES) ? g_counts[i] : 0;
#pragma unroll
    for (int o = 1; o < 32; o <<= 1) {
        int t = __shfl_up_sync(0xffffffffu, v, o);
        if (lane >= o) v += t;
    }
    if (lane == 31) swarp[wid] = v;
    __syncthreads();
    if (wid == 0) {
        int w = swarp[lane];
#pragma unroll
        for (int o = 1; o < 32; o <<= 1) {
            int t = __shfl_up_sync(0xffffffffu, w, o);
            if (lane >= o) w += t;
        }
        swarp[lane] = w;
    }
    __syncthreads();
    if (wid > 0) v += swarp[wid - 1];
    if (i < N_NODES) g_tmp[i] = v;
    if (tid == SCAN_B - 1) g_bsum[blockIdx.x] = v;
}

__global__ void k_scan_fin() {
    PDL_TRIGGER();
    __shared__ int soff;
    int tid = threadIdx.x;
    PDL_WAIT();
    if (tid < 32) {
        int v = 0;
        for (int j = tid; j < (int)blockIdx.x; j += 32) v += g_bsum[j];
#pragma unroll
        for (int o = 16; o > 0; o >>= 1) v += __shfl_xor_sync(0xffffffffu, v, o);
        if (tid == 0) soff = v;
    }
    __syncthreads();
    int off = soff;
    int i = blockIdx.x * SCAN_B + tid;
    if (i < N_NODES) {
        int incl = g_tmp[i] + off;
        int c = g_counts[i];
        int excl = incl - c;
        g_rowptr[i] = excl;
        g_cursor[i] = excl;
        g_counts[i] = 0;                 // restore invariant for next replay
        if (i == N_NODES - 1) g_rowptr[N_NODES] = incl;
    }
}

__global__ void k_scatter(const int* __restrict__ src, const int* __restrict__ dst,
                          const float* __restrict__ ew) {
    PDL_TRIGGER();
    int e2 = blockIdx.x * blockDim.x + threadIdx.x;
    bool ok = (2 * e2 < N_EDGES);
    int2 s = make_int2(0, 0), d = make_int2(0, 0);
    float2 w = make_float2(0.f, 0.f);
    if (ok) {
        s = __ldg((const int2*)src + e2);
        d = __ldg((const int2*)dst + e2);
        w = __ldg((const float2*)ew + e2);
    }
    PDL_WAIT();
    if (ok) {
        int p0 = atomicAdd(&g_cursor[d.x], 1);
        g_edge[p0] = make_int2(s.x, __float_as_int(w.x));
        int p1 = atomicAdd(&g_cursor[d.y], 1);
        g_edge[p1] = make_int2(s.y, __float_as_int(w.y));
    }
}

// ---------------- aggregation: full warp per node (R6 best) ----------------
__global__ void k_aggr64(int sel) {
    PDL_TRIGGER();
    PDL_WAIT();
    int w = (blockIdx.x * blockDim.x + threadIdx.x) >> 5;
    if (w >= N_NODES) return;
    int lane = threadIdx.x & 31, half = lane >> 4, sl = lane & 15;
    const float4* __restrict__ h4 = (const float4*)g_h[sel];
    int i = g_rowptr[w] + half, e = g_rowptr[w + 1];
    float4 a = make_float4(0.f, 0.f, 0.f, 0.f);
    float4 b = make_float4(0.f, 0.f, 0.f, 0.f);
    for (; i + 2 < e; i += 4) {
        int2 r0 = __ldg(&g_edge[i]);
        int2 r1 = __ldg(&g_edge[i + 2]);
        float4 v0 = __ldg(h4 + r0.x * 16 + sl);
        float4 v1 = __ldg(h4 + r1.x * 16 + sl);
        float w0 = __int_as_float(r0.y), w1 = __int_as_float(r1.y);
        a.x += w0 * v0.x; a.y += w0 * v0.y; a.z += w0 * v0.z; a.w += w0 * v0.w;
        b.x += w1 * v1.x; b.y += w1 * v1.y; b.z += w1 * v1.z; b.w += w1 * v1.w;
    }
    if (i < e) {
        int2 r = __ldg(&g_edge[i]);
        float4 v = __ldg(h4 + r.x * 16 + sl);
        float ww = __int_as_float(r.y);
        a.x += ww * v.x; a.y += ww * v.y; a.z += ww * v.z; a.w += ww * v.w;
    }
    a.x += b.x; a.y += b.y; a.z += b.z; a.w += b.w;
    a.x += __shfl_xor_sync(0xffffffffu, a.x, 16);
    a.y += __shfl_xor_sync(0xffffffffu, a.y, 16);
    a.z += __shfl_xor_sync(0xffffffffu, a.z, 16);
    a.w += __shfl_xor_sync(0xffffffffu, a.w, 16);
    if (half == 0) ((float4*)(g_aggr + (size_t)w * 64))[sl] = a;
}

// ---------------- fused layer 0: aggregate(13) + dual-GEMM 13->64 ----------
// 64 nodes/block, 256 threads. Aggregation: 8 warps x 8 nodes, 8 edge-slots x
// 4 lanes x float4 over padded x16. sA stride 20 (float4-aligned, conflict-free).
__global__ __launch_bounds__(256) void k_layer0(
    const float* __restrict__ x,
    const float* __restrict__ Wrel, const float* __restrict__ brel,
    const float* __restrict__ Wroot) {
    PDL_TRIGGER();
    __shared__ __align__(16) float sW[2 * 13 * 64];
    __shared__ float sb[64];
    __shared__ __align__(16) float sA[64 * 20];
    int tid = threadIdx.x, lane = tid & 31, wid = tid >> 5;
    for (int idx = tid; idx < 13 * 64; idx += 256) {   // harness inputs
        sW[idx]           = Wrel[idx];
        sW[13 * 64 + idx] = Wroot[idx];
    }
    if (tid < 64) sb[tid] = brel[tid];
    PDL_WAIT();

    // aggregation: warp wid handles nodes wid*8 .. wid*8+7
    {
        int grp = lane >> 2, sl = lane & 3;
        const float4* __restrict__ x4 = (const float4*)g_x16;
        for (int n = 0; n < 8; n++) {
            int loc = wid * 8 + n;
            int node = blockIdx.x * 64 + loc;
            float4 a = make_float4(0.f, 0.f, 0.f, 0.f);
            if (node < N_NODES) {
                int i = g_rowptr[node] + grp, e = g_rowptr[node + 1];
                for (; i < e; i += 8) {
                    int2 r = __ldg(&g_edge[i]);
                    float4 v = __ldg(x4 + r.x * 4 + sl);
                    float ww = __int_as_float(r.y);
                    a.x += ww * v.x; a.y += ww * v.y; a.z += ww * v.z; a.w += ww * v.w;
                }
            }
#pragma unroll
            for (int o = 4; o < 32; o <<= 1) {
                a.x += __shfl_xor_sync(0xffffffffu, a.x, o);
                a.y += __shfl_xor_sync(0xffffffffu, a.y, o);
                a.z += __shfl_xor_sync(0xffffffffu, a.z, o);
                a.w += __shfl_xor_sync(0xffffffffu, a.w, o);
            }
            if (grp == 0) *(float4*)(sA + loc * 20 + sl * 4) = a;
        }
    }
    __syncthreads();

    // dual GEMM: thread = (node local, 16-col group)
    int loc  = tid >> 2;
    int node = blockIdx.x * 64 + loc;
    int cq   = (tid & 3) * 4;
    int c0   = cq * 4;
    if (node >= N_NODES) return;
    float acc[16];
#pragma unroll
    for (int j = 0; j < 16; j++) acc[j] = sb[c0 + j];
    const float4* sWrel4  = (const float4*)sW;
    const float4* sWroot4 = (const float4*)(sW + 13 * 64);
#pragma unroll
    for (int k = 0; k < 13; k++) {
        float a  = sA[loc * 20 + k];
        float hk = __ldg(&x[node * 13 + k]);
#pragma unroll
        for (int j = 0; j < 4; j++) {
            float4 wr = sWrel4[k * 16 + cq + j];
            float4 ws = sWroot4[k * 16 + cq + j];
            acc[4 * j + 0] += a * wr.x + hk * ws.x;
            acc[4 * j + 1] += a * wr.y + hk * ws.y;
            acc[4 * j + 2] += a * wr.z + hk * ws.z;
            acc[4 * j + 3] += a * wr.w + hk * ws.w;
        }
    }
    float4* o4 = (float4*)(g_h[0] + (size_t)node * 64 + c0);
#pragma unroll
    for (int j = 0; j < 4; j++) {
        float4 v;
        v.x = fmaxf(acc[4 * j + 0], 0.f); v.y = fmaxf(acc[4 * j + 1], 0.f);
        v.z = fmaxf(acc[4 * j + 2], 0.f); v.w = fmaxf(acc[4 * j + 3], 0.f);
        o4[j] = v;
    }
}

// ---------------- GEMM 64->64 via bf16 3-term MMA (fast cvt staging) -------
#define AW 68   // padded word stride (bank-conflict-free fragment loads)
template <bool FINAL>
__global__ __launch_bounds__(256) void k_gemm64_mma(
    const float* __restrict__ Wrel, const float* __restrict__ brel,
    const float* __restrict__ Wroot,
    const float* __restrict__ Wrel4, const float* __restrict__ b4,
    const float* __restrict__ Wroot4,
    int insel, int outsel) {
    PDL_TRIGGER();
    extern __shared__ unsigned smem_u[];
    unsigned* sAhi = smem_u;                    // 128*AW
    unsigned* sAlo = sAhi + 128 * AW;           // 128*AW
    unsigned* sWhi = sAlo + 128 * AW;           // 64*AW
    unsigned* sWlo = sWhi + 64 * AW;            // 64*AW
    float*    sb   = (float*)(sWlo + 64 * AW);  // 64

    int tid = threadIdx.x;
    const float* __restrict__ hin = g_h[insel];
    int nbase = blockIdx.x * 128;

    if (tid < 64) sb[tid] = brel[tid];

    // stage W transposed (harness inputs: pre-wait). word w covers k = 2w,2w+1
    for (int p = tid; p < 64 * 64; p += 256) {
        int col = p >> 6, w = p & 63;
        int k = 2 * w;
        float f0, f1;
        if (k < 64) { f0 = __ldg(&Wrel[k * 64 + col]);         f1 = __ldg(&Wrel[(k + 1) * 64 + col]); }
        else        { f0 = __ldg(&Wroot[(k - 64) * 64 + col]); f1 = __ldg(&Wroot[(k - 63) * 64 + col]); }
        unsigned hi = cvt_bf2(f0, f1);
        sWhi[col * AW + w] = hi;
        sWlo[col * AW + w] = cvt_bf2(f0 - bf_lo(hi), f1 - bf_hi(hi));
    }
    PDL_WAIT();
    // stage A (float4 loads, 8 iters/thread): aggr -> words 0..31, h -> 32..63
    for (int p = tid; p < 128 * 16; p += 256) {
        int ln = p >> 4, w4 = p & 15;             // words 2*w4, 2*w4+1
        int node = nbase + ln;
        if (node >= N_NODES) node = N_NODES - 1;
        float4 va = __ldg((const float4*)(g_aggr + (size_t)node * 64) + w4);
        float4 vh = __ldg((const float4*)(hin    + (size_t)node * 64) + w4);
        unsigned a0 = cvt_bf2(va.x, va.y), a1 = cvt_bf2(va.z, va.w);
        sAhi[ln * AW + 2 * w4]     = a0;
        sAhi[ln * AW + 2 * w4 + 1] = a1;
        sAlo[ln * AW + 2 * w4]     = cvt_bf2(va.x - bf_lo(a0), va.y - bf_hi(a0));
        sAlo[ln * AW + 2 * w4 + 1] = cvt_bf2(va.z - bf_lo(a1), va.w - bf_hi(a1));
        unsigned h0 = cvt_bf2(vh.x, vh.y), h1 = cvt_bf2(vh.z, vh.w);
        sAhi[ln * AW + 32 + 2 * w4]     = h0;
        sAhi[ln * AW + 32 + 2 * w4 + 1] = h1;
        sAlo[ln * AW + 32 + 2 * w4]     = cvt_bf2(vh.x - bf_lo(h0), vh.y - bf_hi(h0));
        sAlo[ln * AW + 32 + 2 * w4 + 1] = cvt_bf2(vh.z - bf_lo(h1), vh.w - bf_hi(h1));
    }
    __syncthreads();

    int warp = tid >> 5, lane = tid & 31;
    int r = lane >> 2, q = lane & 3;
    int mb = warp * 16;

    float acc[8][4];
#pragma unroll
    for (int j = 0; j < 8; j++) {
        float b0 = sb[j * 8 + 2 * q], b1 = sb[j * 8 + 2 * q + 1];
        acc[j][0] = b0; acc[j][1] = b1; acc[j][2] = b0; acc[j][3] = b1;
    }

    int arow0 = (mb + r) * AW, arow1 = (mb + r + 8) * AW;
#pragma unroll
    for (int ks = 0; ks < 8; ks++) {
        int kw = ks * 8 + q;
        unsigned ah0 = sAhi[arow0 + kw],     ah1 = sAhi[arow1 + kw];
        unsigned ah2 = sAhi[arow0 + kw + 4], ah3 = sAhi[arow1 + kw + 4];
        unsigned al0 = sAlo[arow0 + kw],     al1 = sAlo[arow1 + kw];
        unsigned al2 = sAlo[arow0 + kw + 4], al3 = sAlo[arow1 + kw + 4];
#pragma unroll
        for (int j = 0; j < 8; j++) {
            int brow = (j * 8 + r) * AW + ks * 8 + q;
            unsigned bh0 = sWhi[brow], bh1 = sWhi[brow + 4];
            unsigned bl0 = sWlo[brow], bl1 = sWlo[brow + 4];
            mma_bf16(acc[j], ah0, ah1, ah2, ah3, bh0, bh1);
            mma_bf16(acc[j], ah0, ah1, ah2, ah3, bl0, bl1);
            mma_bf16(acc[j], al0, al1, al2, al3, bh0, bh1);
        }
    }

    int n0 = nbase + mb + r;      // row of c0/c1
    int n1 = n0 + 8;              // row of c2/c3
    if (FINAL) {
        float pt0 = 0.f, pr0 = 0.f, pt1 = 0.f, pr1 = 0.f;
#pragma unroll
        for (int j = 0; j < 8; j++) {
            int c = j * 8 + 2 * q;
            float w0 = __ldg(&Wrel4[c]),  w1 = __ldg(&Wrel4[c + 1]);
            float s0 = __ldg(&Wroot4[c]), s1 = __ldg(&Wroot4[c + 1]);
            float u;
            u = fmaxf(acc[j][0], 0.f); pt0 += u * w0; pr0 += u * s0;
            u = fmaxf(acc[j][1], 0.f); pt0 += u * w1; pr0 += u * s1;
            u = fmaxf(acc[j][2], 0.f); pt1 += u * w0; pr1 += u * s0;
            u = fmaxf(acc[j][3], 0.f); pt1 += u * w1; pr1 += u * s1;
        }
        pt0 += __shfl_xor_sync(0xffffffffu, pt0, 1);
        pt0 += __shfl_xor_sync(0xffffffffu, pt0, 2);
        pr0 += __shfl_xor_sync(0xffffffffu, pr0, 1);
        pr0 += __shfl_xor_sync(0xffffffffu, pr0, 2);
        pt1 += __shfl_xor_sync(0xffffffffu, pt1, 1);
        pt1 += __shfl_xor_sync(0xffffffffu, pt1, 2);
        pr1 += __shfl_xor_sync(0xffffffffu, pr1, 1);
        pr1 += __shfl_xor_sync(0xffffffffu, pr1, 2);
        float bb = __ldg(&b4[0]);
        if (q == 0) {
            if (n0 < N_NODES) { g_t[n0] = pt0; g_r[n0] = pr0 + bb; }
            if (n1 < N_NODES) { g_t[n1] = pt1; g_r[n1] = pr1 + bb; }
        }
    } else {
        float* ob = g_h[outsel];
#pragma unroll
        for (int j = 0; j < 8; j++) {
            int c = j * 8 + 2 * q;
            if (n0 < N_NODES)
                *(float2*)(ob + (size_t)n0 * 64 + c) =
                    make_float2(fmaxf(acc[j][0], 0.f), fmaxf(acc[j][1], 0.f));
            if (n1 < N_NODES)
                *(float2*)(ob + (size_t)n1 * 64 + c) =
                    make_float2(fmaxf(acc[j][2], 0.f), fmaxf(acc[j][3], 0.f));
        }
    }
}

// ---------------- final: out = sigmoid(segsum(w * t[src]) + r) -------------
__global__ void k_final(float* __restrict__ out) {
    PDL_TRIGGER();
    PDL_WAIT();
    int gw   = (blockIdx.x * blockDim.x + threadIdx.x) >> 5;
    int lane = threadIdx.x & 31;
    if (gw >= N_NODES) return;
    int start = g_rowptr[gw], end = g_rowptr[gw + 1];
    float acc = 0.f;
    for (int e = start + lane; e < end; e += 32) {
        int2 er = __ldg(&g_edge[e]);
        acc += __int_as_float(er.y) * __ldg(&g_t[er.x]);
    }
#pragma unroll
    for (int o = 16; o > 0; o >>= 1)
        acc += __shfl_xor_sync(0xffffffffu, acc, o);
    if (lane == 0) {
        float z = acc + g_r[gw];
        out[gw] = 1.f / (1.f + expf(-z));
    }
}

// ---------------- launch helpers ----------------
template <typename F, typename... Args>
static void launch_pdl(F f, dim3 g, dim3 b, size_t sm, Args... args) {
    cudaLaunchConfig_t cfg = {};
    cfg.gridDim = g;
    cfg.blockDim = b;
    cfg.dynamicSmemBytes = sm;
    cfg.stream = 0;
    cudaLaunchAttribute at[1];
    at[0].id = cudaLaunchAttributeProgrammaticStreamSerialization;
    at[0].val.programmaticStreamSerializationAllowed = 1;
    cfg.attrs = at;
    cfg.numAttrs = 1;
    cudaLaunchKernelEx(&cfg, f, args...);
}

extern "C" void kernel_launch(void* const* d_in, const int* in_sizes, int n_in,
                              void* d_out, int out_size) {
    const float* x  = (const float*)d_in[0];
    const int*   ei = (const int*)d_in[1];
    const float* ew = (const float*)d_in[2];
    const int* src = ei;
    const int* dst = ei + N_EDGES;

    const float* Wrel[5], * brel[5], * Wroot[5];
    for (int l = 0; l < 5; l++) {
        Wrel[l]  = (const float*)d_in[3 + 3 * l];
        brel[l]  = (const float*)d_in[4 + 3 * l];
        Wroot[l] = (const float*)d_in[5 + 3 * l];
    }
    float* out = (float*)d_out;

    const int SMEM_MMA = (128 * AW * 2 + 64 * AW * 2 + 64) * 4;   // 104704 B
    cudaFuncSetAttribute(k_gemm64_mma<false>,
                         cudaFuncAttributeMaxDynamicSharedMemorySize, SMEM_MMA);
    cudaFuncSetAttribute(k_gemm64_mma<true>,
                         cudaFuncAttributeMaxDynamicSharedMemorySize, SMEM_MMA);

    const int TB = 256;
    dim3 B(TB);
    int gE2  = (N_EDGES / 2 + TB - 1) / TB;       // 2 edges/thread (covers padx)
    int gW   = (N_NODES * 32 + TB - 1) / TB;      // warp-per-node
    int g64  = (N_NODES + 63) / 64;
    int g128 = (N_NODES + 127) / 128;

    // CSR build (g_counts zero by invariant)
    launch_pdl(k_hist, dim3(gE2), B, 0, dst, x);
    launch_pdl(k_scan_part, dim3(SCAN_NB), dim3(SCAN_B), 0);
    launch_pdl(k_scan_fin,  dim3(SCAN_NB), dim3(SCAN_B), 0);
    launch_pdl(k_scatter, dim3(gE2), B, 0, src, dst, ew);

    // layer 0: 13 -> 64 (fused aggregation + GEMM)
    launch_pdl(k_layer0, dim3(g64), B, 0, x, Wrel[0], brel[0], Wroot[0]);

    // layers 1-3: 64 -> 64 (layer 3 folds the 64->1 projection of layer 4)
    launch_pdl(k_aggr64, dim3(gW), B, 0, 0);
    launch_pdl(k_gemm64_mma<false>, dim3(g128), B, (size_t)SMEM_MMA,
               Wrel[1], brel[1], Wroot[1],
               (const float*)nullptr, (const float*)nullptr, (const float*)nullptr, 0, 1);
    launch_pdl(k_aggr64, dim3(gW), B, 0, 1);
    launch_pdl(k_gemm64_mma<false>, dim3(g128), B, (size_t)SMEM_MMA,
               Wrel[2], brel[2], Wroot[2],
               (const float*)nullptr, (const float*)nullptr, (const float*)nullptr, 1, 0);
    launch_pdl(k_aggr64, dim3(gW), B, 0, 0);
    launch_pdl(k_gemm64_mma<true>, dim3(g128), B, (size_t)SMEM_MMA,
               Wrel[3], brel[3], Wroot[3],
               Wrel[4], brel[4], Wroot[4], 0, 0);

    // layer 4 aggregation (scalar) + sigmoid
    launch_pdl(k_final, dim3(gW), B, 0, out);
}